// round 1
// baseline (speedup 1.0000x reference)
#include <cuda_runtime.h>
#include <cuda_bf16.h>
#include <stdint.h>

// Problem: out[m] = x[m]·W + b + 0.5*||x[m]V||^2 - 0.5*(sum_i x[m,i])^2 * ||V.sum(0)||^2
// x: (16384, 4096) f32, W: (1,4096) f32, b: (1,) f32, V: (4096,128) f32, out: (16384,1) f32

#define MROWS 16384
#define KDIM  4096   // reduction dim
#define NDIM  128    // V columns
#define KC    32     // K-chunk per stage
#define SP    40     // padded smem row stride (bf16 elems) -> conflict-free frags
#define NCHUNK (KDIM / KC)

// device scratch (no allocations allowed in kernel_launch)
__device__ __nv_bfloat16 g_Vt[NDIM * KDIM];  // V transposed, bf16: [n][k]
__device__ float g_s[NDIM];                  // column sums of V
__device__ float g_s2;                       // ||s||^2

// ---------------- pre-kernels ----------------

__global__ void prep_kernel(const float* __restrict__ V) {
    int n = blockIdx.x;      // 0..127
    int t = threadIdx.x;     // 256 threads
    float acc = 0.f;
    for (int k = t; k < KDIM; k += 256) {
        float v = V[(size_t)k * NDIM + n];
        acc += v;
        g_Vt[(size_t)n * KDIM + k] = __float2bfloat16(v);
    }
    __shared__ float sh[256];
    sh[t] = acc;
    __syncthreads();
    for (int s = 128; s > 0; s >>= 1) {
        if (t < s) sh[t] += sh[t + s];
        __syncthreads();
    }
    if (t == 0) g_s[n] = sh[0];
}

__global__ void s2_kernel() {
    int t = threadIdx.x;     // 128 threads
    __shared__ float sh[128];
    float v = g_s[t];
    sh[t] = v * v;
    __syncthreads();
    for (int s = 64; s > 0; s >>= 1) {
        if (t < s) sh[t] += sh[t + s];
        __syncthreads();
    }
    if (t == 0) g_s2 = sh[0];
}

// ---------------- main kernel ----------------

__device__ __forceinline__ uint32_t pack_bf16(float lo, float hi) {
    __nv_bfloat162 h = __float22bfloat162_rn(make_float2(lo, hi));
    return *reinterpret_cast<uint32_t*>(&h);
}

#define MMA_OP(d, a0, a1, a2, a3, b0, b1)                                  \
    asm volatile(                                                          \
        "mma.sync.aligned.m16n8k16.row.col.f32.bf16.bf16.f32 "             \
        "{%0,%1,%2,%3}, {%4,%5,%6,%7}, {%8,%9}, {%0,%1,%2,%3};"            \
        : "+f"((d)[0]), "+f"((d)[1]), "+f"((d)[2]), "+f"((d)[3])           \
        : "r"(a0), "r"(a1), "r"(a2), "r"(a3), "r"(b0), "r"(b1))

__global__ void __launch_bounds__(256, 1) fm_main_kernel(
    const float* __restrict__ x, const float* __restrict__ W,
    const float* __restrict__ bias, float* __restrict__ out)
{
    __shared__ __nv_bfloat16 xs[2][128 * SP];  // x tile bf16 [row][k]
    __shared__ __nv_bfloat16 vs[2][128 * SP];  // V^T tile bf16 [n][k]
    __shared__ float red[128][4];              // term1 partials per n-quad
    __shared__ float xsum_s[128];
    __shared__ float xw_s[128];

    const int t     = threadIdx.x;
    const int warp  = t >> 5;
    const int lane  = t & 31;
    const int g     = lane >> 2;   // group id (0..7)
    const int tid4  = lane & 3;    // thread-in-group
    const int strip = warp >> 2;   // m-strip (0..1): 64 rows each
    const int nq    = warp & 3;    // n-quad (0..3): 32 cols each
    const int mbase = blockIdx.x * 128;

    // staging assignment: 2 threads per row (k halves of 16)
    const int srow  = t >> 1;
    const int shalf = t & 1;
    const float* xp = x + (size_t)(mbase + srow) * KDIM + shalf * 16;
    const __nv_bfloat16* vp = g_Vt + (size_t)srow * KDIM + shalf * 16;
    const float* wp = W + shalf * 16;

    float acc[4][4][4];
#pragma unroll
    for (int a = 0; a < 4; a++)
#pragma unroll
        for (int bb = 0; bb < 4; bb++)
#pragma unroll
            for (int c = 0; c < 4; c++) acc[a][bb][c] = 0.f;

    float sx = 0.f, sw = 0.f;   // fp32 row-sum and row·W partials

    float4 xr[4];
    uint4  vr[2];
    float4 wr[4];

#define LOAD_CHUNK(k0)                                                     \
    do {                                                                   \
        const float4* xq = (const float4*)(xp + (k0));                     \
        xr[0] = __ldg(xq + 0); xr[1] = __ldg(xq + 1);                      \
        xr[2] = __ldg(xq + 2); xr[3] = __ldg(xq + 3);                      \
        const uint4* vq = (const uint4*)(vp + (k0));                       \
        vr[0] = vq[0]; vr[1] = vq[1];                                      \
        const float4* wq = (const float4*)(wp + (k0));                     \
        wr[0] = __ldg(wq + 0); wr[1] = __ldg(wq + 1);                      \
        wr[2] = __ldg(wq + 2); wr[3] = __ldg(wq + 3);                      \
    } while (0)

#define STAGE_CHUNK(bufi)                                                  \
    do {                                                                   \
        sx += xr[0].x + xr[0].y + xr[0].z + xr[0].w                        \
            + xr[1].x + xr[1].y + xr[1].z + xr[1].w                        \
            + xr[2].x + xr[2].y + xr[2].z + xr[2].w                        \
            + xr[3].x + xr[3].y + xr[3].z + xr[3].w;                       \
        sw += xr[0].x * wr[0].x + xr[0].y * wr[0].y                        \
            + xr[0].z * wr[0].z + xr[0].w * wr[0].w                        \
            + xr[1].x * wr[1].x + xr[1].y * wr[1].y                        \
            + xr[1].z * wr[1].z + xr[1].w * wr[1].w                        \
            + xr[2].x * wr[2].x + xr[2].y * wr[2].y                        \
            + xr[2].z * wr[2].z + xr[2].w * wr[2].w                        \
            + xr[3].x * wr[3].x + xr[3].y * wr[3].y                        \
            + xr[3].z * wr[3].z + xr[3].w * wr[3].w;                       \
        uint4 p0, p1;                                                      \
        p0.x = pack_bf16(xr[0].x, xr[0].y);                                \
        p0.y = pack_bf16(xr[0].z, xr[0].w);                                \
        p0.z = pack_bf16(xr[1].x, xr[1].y);                                \
        p0.w = pack_bf16(xr[1].z, xr[1].w);                                \
        p1.x = pack_bf16(xr[2].x, xr[2].y);                                \
        p1.y = pack_bf16(xr[2].z, xr[2].w);                                \
        p1.z = pack_bf16(xr[3].x, xr[3].y);                                \
        p1.w = pack_bf16(xr[3].z, xr[3].w);                                \
        uint4* xd = (uint4*)&xs[bufi][srow * SP + shalf * 16];             \
        xd[0] = p0; xd[1] = p1;                                            \
        uint4* vd = (uint4*)&vs[bufi][srow * SP + shalf * 16];             \
        vd[0] = vr[0]; vd[1] = vr[1];                                      \
    } while (0)

    // prologue: stage chunk 0
    LOAD_CHUNK(0);
    STAGE_CHUNK(0);
    __syncthreads();

    for (int c = 0; c < NCHUNK; c++) {
        const int bufi = c & 1;
        const bool more = (c + 1 < NCHUNK);
        if (more) LOAD_CHUNK((c + 1) * KC);   // overlap DRAM with MMA

        const __nv_bfloat16* xb = xs[bufi];
        const __nv_bfloat16* vb = vs[bufi];

#pragma unroll
        for (int ks = 0; ks < 2; ks++) {
            const int kk = ks * 16;
            uint32_t a[4][4];
#pragma unroll
            for (int mf = 0; mf < 4; mf++) {
                const int r0 = strip * 64 + mf * 16 + g;
                const __nv_bfloat16* base0 = xb + r0 * SP + kk + tid4 * 2;
                const __nv_bfloat16* base1 = base0 + 8 * SP;
                a[mf][0] = *(const uint32_t*)(base0);
                a[mf][1] = *(const uint32_t*)(base1);
                a[mf][2] = *(const uint32_t*)(base0 + 8);
                a[mf][3] = *(const uint32_t*)(base1 + 8);
            }
            uint32_t bfr[4][2];
#pragma unroll
            for (int nf = 0; nf < 4; nf++) {
                const int nc = nq * 32 + nf * 8 + g;
                const __nv_bfloat16* bp = vb + nc * SP + kk + tid4 * 2;
                bfr[nf][0] = *(const uint32_t*)(bp);
                bfr[nf][1] = *(const uint32_t*)(bp + 8);
            }
#pragma unroll
            for (int mf = 0; mf < 4; mf++)
#pragma unroll
                for (int nf = 0; nf < 4; nf++)
                    MMA_OP(acc[mf][nf], a[mf][0], a[mf][1], a[mf][2], a[mf][3],
                           bfr[nf][0], bfr[nf][1]);
        }

        if (more) STAGE_CHUNK(bufi ^ 1);
        __syncthreads();
    }

    // fp32 side sums: combine the 2 k-halves of each row
    sx += __shfl_xor_sync(0xffffffffu, sx, 1);
    sw += __shfl_xor_sync(0xffffffffu, sw, 1);
    if (shalf == 0) {
        xsum_s[srow] = sx;
        xw_s[srow]   = sw;
    }

    // term1 = sum over n of xv^2 ; reduce each m16 tile
#pragma unroll
    for (int mf = 0; mf < 4; mf++) {
        float p0 = 0.f, p1 = 0.f;
#pragma unroll
        for (int nf = 0; nf < 4; nf++) {
            p0 += acc[mf][nf][0] * acc[mf][nf][0] + acc[mf][nf][1] * acc[mf][nf][1];
            p1 += acc[mf][nf][2] * acc[mf][nf][2] + acc[mf][nf][3] * acc[mf][nf][3];
        }
        p0 += __shfl_xor_sync(0xffffffffu, p0, 1);
        p0 += __shfl_xor_sync(0xffffffffu, p0, 2);
        p1 += __shfl_xor_sync(0xffffffffu, p1, 1);
        p1 += __shfl_xor_sync(0xffffffffu, p1, 2);
        if (tid4 == 0) {
            red[strip * 64 + mf * 16 + g][nq]     = p0;
            red[strip * 64 + mf * 16 + 8 + g][nq] = p1;
        }
    }
    __syncthreads();

    if (t < 128) {
        float term1 = red[t][0] + red[t][1] + red[t][2] + red[t][3];
        float s_    = xsum_s[t];
        out[mbase + t] = xw_s[t] + bias[0] + 0.5f * term1 - 0.5f * s_ * s_ * g_s2;
    }
}

// ---------------- launch ----------------

extern "C" void kernel_launch(void* const* d_in, const int* in_sizes, int n_in,
                              void* d_out, int out_size) {
    (void)in_sizes; (void)n_in; (void)out_size;
    const float* x = (const float*)d_in[0];
    const float* W = (const float*)d_in[1];
    const float* b = (const float*)d_in[2];
    const float* V = (const float*)d_in[3];
    float* out = (float*)d_out;

    prep_kernel<<<NDIM, 256>>>(V);       // V^T bf16 + column sums
    s2_kernel<<<1, 128>>>();             // ||s||^2 (deterministic reduce)
    fm_main_kernel<<<MROWS / 128, 256>>>(x, W, b, out);
}